// round 16
// baseline (speedup 1.0000x reference)
#include <cuda_runtime.h>
#include <cstdint>

#define H 256
#define DD 64
#define NPAIR 128
#define NQT 4                     // t-quarters
#define NBM (NQT * NPAIR)         // 512 k_main blocks: (pair, quarter)

// ---------------- persistent device state (no allocations) ----------------
__device__ __align__(16) float g_G[H * H];          // Gram (symmetric)
__device__ __align__(16) float g_h[H], g_h1[H], g_h2[H], g_u3[H], g_h2s[H], g_h4s2[H];
__device__ __align__(16) float g_QRZU[NPAIR][8];    // zeroed by k_pre each replay
__device__ __align__(16) float g_aLY[NPAIR][6];     // {a0,L0,Y0,a1,L1,Y1}
__device__ unsigned int g_done = 0;

// ---------------- kernel 1: uniform Gram + fused per-row chain (128 blocks) ----
__global__ __launch_bounds__(256) void k_pre(
    const float* __restrict__ x,  const float* __restrict__ W1,
    const float* __restrict__ b1)
{
    __shared__ float srow[2][DD];
    __shared__ float sx[DD];
    int tid = threadIdx.x;
    int wid = tid >> 5, lane = tid & 31;
    int m0 = 2 * blockIdx.x;

    if (tid < 2 * DD) srow[tid >> 6][tid & 63] = W1[(m0 + (tid >> 6)) * DD + (tid & 63)];
    else if (tid < 2 * DD + DD) sx[tid - 2 * DD] = x[tid - 2 * DD];
    if (tid >= 192 && tid < 200) g_QRZU[blockIdx.x][tid - 192] = 0.f;
    __syncthreads();

    const float4* myr = (const float4*)(W1 + tid * DD);
    float a0 = 0.f, a1 = 0.f;
#pragma unroll
    for (int i = 0; i < DD / 4; i++) {
        float4 v = __ldg(myr + i);
        a0 += srow[0][4*i]*v.x + srow[0][4*i+1]*v.y + srow[0][4*i+2]*v.z + srow[0][4*i+3]*v.w;
        a1 += srow[1][4*i]*v.x + srow[1][4*i+1]*v.y + srow[1][4*i+2]*v.z + srow[1][4*i+3]*v.w;
    }
    g_G[(m0 + 0) * H + tid] = a0;
    g_G[(m0 + 1) * H + tid] = a1;

    if (wid < 2) {
        float v0 = srow[wid][lane], v1 = srow[wid][lane + 32];
        float z = v0 * sx[lane] + v1 * sx[lane + 32];
        float s = v0 * v0 + v1 * v1;
#pragma unroll
        for (int o = 16; o > 0; o >>= 1) {
            z += __shfl_down_sync(0xFFFFFFFFu, z, o);
            s += __shfl_down_sync(0xFFFFFFFFu, s, o);
        }
        if (lane == 0) {
            int m = m0 + wid;
            z += b1[m];
            float h = tanhf(z), w = 1.f - h * h;
            float h2 = -2.f * h * w;
            float h3 = (4.f * h * h - 2.f * w) * w;
            float h4 = (16.f * w - 8.f * h * h) * h * w;
            g_h[m]    = h;
            g_h1[m]   = w;
            g_h2[m]   = h2;
            g_u3[m]   = h3 * s;
            g_h2s[m]  = h2 * s;
            g_h4s2[m] = h4 * s * s;
        }
    }
}

// ---------------- kernel 2: streaming contraction, grid = (pair, t-quarter) ----------------
__global__ __launch_bounds__(256, 4) void k_main(
    const float* __restrict__ W2, const float* __restrict__ W3,
    const float* __restrict__ b2, float* __restrict__ out)
{
    __shared__ float  sP[16 * 16 * 16];  // phase-1 partials [ms][ts][16] = 16KB
    __shared__ float4 sAB[H];            // {A0, A1, B0, B1} (4KB)
    __shared__ float  sU0g[64], sU1g[64];
    __shared__ float  sred[2][8];
    __shared__ float  sredA[8][6];
    __shared__ double sdr[8];

    int tid = threadIdx.x;
    int bx = blockIdx.x;
    int p = bx >> 2, qt = bx & 3;
    int wid = tid >> 5, lane = tid & 31;
    int n0 = 2 * p;

    // ---- setup: coefficient vectors (+ a/L/Y for qt==0) ----
    float aa0, aa1, LL0, LL1, YY0, YY1;
    {
        int m = tid;
        float h1 = g_h1[m], h2 = g_h2[m];
        float w20 = __ldg(&W2[n0 * H + m]);
        float w21 = __ldg(&W2[(n0 + 1) * H + m]);
        sAB[m] = make_float4(w20 * h1, w21 * h1, w20 * h2, w21 * h2);
        if (qt == 0) {
            float hh = g_h[m], h2s = g_h2s[m], h4s2 = g_h4s2[m];
            aa0 = w20 * hh;   aa1 = w21 * hh;
            LL0 = w20 * h2s;  LL1 = w21 * h2s;
            YY0 = w20 * h4s2; YY1 = w21 * h4s2;
        }
        // U coefficients for this quarter's 64 t-columns
        if (tid < 64) {
            int gt = qt * 64 + tid;
            float u3 = g_u3[gt];
            sU0g[tid] = __ldg(&W2[n0 * H + gt]) * u3;
            sU1g[tid] = __ldg(&W2[(n0 + 1) * H + gt]) * u3;
        }
    }
    if (qt == 0) {
        float v[6] = {aa0, LL0, YY0, aa1, LL1, YY1};
#pragma unroll
        for (int k = 0; k < 6; k++) {
            float t = v[k];
#pragma unroll
            for (int o = 16; o > 0; o >>= 1) t += __shfl_down_sync(0xFFFFFFFFu, t, o);
            v[k] = t;
        }
        if (lane == 0) {
#pragma unroll
            for (int k = 0; k < 6; k++) sredA[wid][k] = v[k];
        }
    }
    __syncthreads();
    if (qt == 0 && tid < 6) {
        float t = 0.f;
#pragma unroll
        for (int w = 0; w < 8; w++) t += sredA[w][tid];
        g_aLY[p][tid] = t;
    }

    // ---- phase 1: pipelined G stream; thread = (ms = tid>>4, ts = tid&15) ----
    // t-cols: float4 index qt*16 + ts ; m-rows: 16*ms .. 16*ms+15
    int ms = tid >> 4, ts = tid & 15;
    float M0[4] = {0,0,0,0}, M1[4] = {0,0,0,0};
    float P0[4] = {0,0,0,0}, P1[4] = {0,0,0,0};

    const float4* Gp = (const float4*)g_G + (16 * ms) * (H / 4) + qt * 16 + ts;
    const float4* abp = sAB + 16 * ms;

    float4 buf[2][4];
#pragma unroll
    for (int u = 0; u < 4; u++) buf[0][u] = __ldg(Gp + u * (H / 4));

#pragma unroll
    for (int bb = 0; bb < 4; bb++) {
        int cur = bb & 1, nxt = cur ^ 1;
        if (bb < 3) {
#pragma unroll
            for (int u = 0; u < 4; u++)
                buf[nxt][u] = __ldg(Gp + (4 * (bb + 1) + u) * (H / 4));
        }
#pragma unroll
        for (int u = 0; u < 4; u++) {
            float4 ab = abp[4 * bb + u];
            float4 g = buf[cur][u];
            M0[0] += ab.x * g.x;  M0[1] += ab.x * g.y;  M0[2] += ab.x * g.z;  M0[3] += ab.x * g.w;
            M1[0] += ab.y * g.x;  M1[1] += ab.y * g.y;  M1[2] += ab.y * g.z;  M1[3] += ab.y * g.w;
            float gg0 = g.x * g.x, gg1 = g.y * g.y, gg2 = g.z * g.z, gg3 = g.w * g.w;
            P0[0] += ab.z * gg0;  P0[1] += ab.z * gg1;  P0[2] += ab.z * gg2;  P0[3] += ab.z * gg3;
            P1[0] += ab.w * gg0;  P1[1] += ab.w * gg1;  P1[2] += ab.w * gg2;  P1[3] += ab.w * gg3;
        }
    }
    {
        float4* sp = (float4*)(sP + (ms * 16 + ts) * 16);
        sp[0] = make_float4(M0[0], M0[1], M0[2], M0[3]);
        sp[1] = make_float4(M1[0], M1[1], M1[2], M1[3]);
        sp[2] = make_float4(P0[0], P0[1], P0[2], P0[3]);
        sp[3] = make_float4(P1[0], P1[1], P1[2], P1[3]);
    }
    __syncthreads();

    // ---- phase 2: combine ms partials + contraction (threads 0-63; t = tid) ----
    if (tid < 64) {
        int tts = tid >> 2, c = tid & 3;
        float m0 = 0.f, m1 = 0.f, q0 = 0.f, q1 = 0.f;
#pragma unroll
        for (int w = 0; w < 16; w++) {
            const float* sp = sP + (w * 16 + tts) * 16;
            m0 += sp[c];
            m1 += sp[4 + c];
            q0 += sp[8 + c];
            q1 += sp[12 + c];
        }
        int gt = qt * 64 + tid;
        float4 ab = sAB[gt];
        float pv[8];
        pv[0] = ab.x * m0;      pv[1] = ab.z * m0 * m0;
        pv[2] = ab.z * q0;      pv[3] = sU0g[tid] * m0;
        pv[4] = ab.y * m1;      pv[5] = ab.w * m1 * m1;
        pv[6] = ab.w * q1;      pv[7] = sU1g[tid] * m1;
#pragma unroll
        for (int k = 0; k < 8; k++) {
            float v = pv[k];
#pragma unroll
            for (int o = 16; o > 0; o >>= 1) v += __shfl_down_sync(0xFFFFFFFFu, v, o);
            pv[k] = v;
        }
        if (lane == 0) {
#pragma unroll
            for (int k = 0; k < 8; k++) sred[wid][k] = pv[k];
        }
    }
    __syncthreads();
    if (tid < 8) {
        float t = sred[0][tid] + sred[1][tid];
        atomicAdd(&g_QRZU[p][tid], t);
    }

    // ---- global ticket: one block runs the nonlinear tail ----
    __threadfence();
    __shared__ unsigned int slast;
    if (tid == 0) slast = (atomicAdd(&g_done, 1u) == NBM - 1) ? 1u : 0u;
    __syncthreads();
    if (slast) {
        __threadfence();
        int n = tid;
        int pp = n >> 1, sel = n & 1;
        float Q = g_QRZU[pp][4 * sel + 0];
        float R = g_QRZU[pp][4 * sel + 1];
        float Z = g_QRZU[pp][4 * sel + 2];
        float U = g_QRZU[pp][4 * sel + 3];
        float a = g_aLY[pp][3 * sel + 0] + b2[n];
        float L = g_aLY[pp][3 * sel + 1];
        float Y = g_aLY[pp][3 * sel + 2];
        float g = tanhf(a), gw = 1.f - g * g;
        float g1 = gw;
        float g2 = -2.f * g * gw;
        float g3 = (4.f * g * g - 2.f * gw) * gw;
        float g4 = (16.f * gw - 8.f * g * g) * g * gw;
        float val = g4 * Q * Q
                  + g3 * (2.f * L * Q + 4.f * R)
                  + g2 * (L * L + 2.f * Z + 4.f * U)
                  + g1 * Y;
        double d = (double)(__ldg(&W3[n]) * val);
#pragma unroll
        for (int o = 16; o > 0; o >>= 1) d += __shfl_down_sync(0xFFFFFFFFu, d, o);
        if (lane == 0) sdr[wid] = d;
        __syncthreads();
        if (wid == 0) {
            double v = (lane < 8) ? sdr[lane] : 0.0;
#pragma unroll
            for (int o = 4; o > 0; o >>= 1) v += __shfl_down_sync(0xFFu, v, o);
            if (lane == 0) {
                out[0] = (float)v;
                g_done = 0u;       // reset for next graph replay
                __threadfence();
            }
        }
    }
}

// ---------------- launch ----------------
extern "C" void kernel_launch(void* const* d_in, const int* in_sizes, int n_in,
                              void* d_out, int out_size) {
    const float* x  = (const float*)d_in[0];
    const float* W1 = (const float*)d_in[1];
    const float* b1 = (const float*)d_in[2];
    const float* W2 = (const float*)d_in[3];
    const float* b2 = (const float*)d_in[4];
    const float* W3 = (const float*)d_in[5];
    // d_in[6] = b3: does not affect the 4th derivative
    float* out = (float*)d_out;

    k_pre<<<NPAIR, 256>>>(x, W1, b1);
    k_main<<<NBM, 256>>>(W2, W3, b2, out);
}

// round 17
// speedup vs baseline: 1.1577x; 1.1577x over previous
#include <cuda_runtime.h>
#include <cstdint>

#define H 256
#define DD 64
#define NQUAD 64                  // quads of 4 output neurons
#define NQT 4                     // t-quarters
#define NBM (NQUAD * NQT)         // 256 k_main blocks

// ---------------- persistent device state (no allocations) ----------------
__device__ __align__(16) float g_G[H * H];          // Gram (symmetric)
__device__ __align__(16) float g_h[H], g_h1[H], g_h2[H], g_u3[H], g_h2s[H], g_h4s2[H];
__device__ __align__(16) float g_QRZU[NQUAD][16];   // {Q,R,Z,U} x 4 n; zeroed by k_pre
__device__ __align__(16) float g_aLY[NQUAD][12];    // {a,L,Y} x 4 n
__device__ unsigned int g_done = 0;

// ---------------- kernel 1: uniform Gram + fused per-row chain (128 blocks) ----
__global__ __launch_bounds__(256) void k_pre(
    const float* __restrict__ x,  const float* __restrict__ W1,
    const float* __restrict__ b1)
{
    __shared__ float srow[2][DD];
    __shared__ float sx[DD];
    int tid = threadIdx.x;
    int wid = tid >> 5, lane = tid & 31;
    int m0 = 2 * blockIdx.x;

    if (tid < 2 * DD) srow[tid >> 6][tid & 63] = W1[(m0 + (tid >> 6)) * DD + (tid & 63)];
    else if (tid < 2 * DD + DD) sx[tid - 2 * DD] = x[tid - 2 * DD];
    if (blockIdx.x < NQUAD && tid >= 192 && tid < 208) g_QRZU[blockIdx.x][tid - 192] = 0.f;
    __syncthreads();

    const float4* myr = (const float4*)(W1 + tid * DD);
    float a0 = 0.f, a1 = 0.f;
#pragma unroll
    for (int i = 0; i < DD / 4; i++) {
        float4 v = __ldg(myr + i);
        a0 += srow[0][4*i]*v.x + srow[0][4*i+1]*v.y + srow[0][4*i+2]*v.z + srow[0][4*i+3]*v.w;
        a1 += srow[1][4*i]*v.x + srow[1][4*i+1]*v.y + srow[1][4*i+2]*v.z + srow[1][4*i+3]*v.w;
    }
    g_G[(m0 + 0) * H + tid] = a0;
    g_G[(m0 + 1) * H + tid] = a1;

    if (wid < 2) {
        float v0 = srow[wid][lane], v1 = srow[wid][lane + 32];
        float z = v0 * sx[lane] + v1 * sx[lane + 32];
        float s = v0 * v0 + v1 * v1;
#pragma unroll
        for (int o = 16; o > 0; o >>= 1) {
            z += __shfl_down_sync(0xFFFFFFFFu, z, o);
            s += __shfl_down_sync(0xFFFFFFFFu, s, o);
        }
        if (lane == 0) {
            int m = m0 + wid;
            z += b1[m];
            float h = tanhf(z), w = 1.f - h * h;
            float h2 = -2.f * h * w;
            float h3 = (4.f * h * h - 2.f * w) * w;
            float h4 = (16.f * w - 8.f * h * h) * h * w;
            g_h[m]    = h;
            g_h1[m]   = w;
            g_h2[m]   = h2;
            g_u3[m]   = h3 * s;
            g_h2s[m]  = h2 * s;
            g_h4s2[m] = h4 * s * s;
        }
    }
}

// ---------------- kernel 2: streaming contraction, grid = (quad, t-quarter) ----------------
// Block (q, qt): output neurons n0..n0+3, t-columns [64*qt, 64*qt+64).
//   M[n,t] = sum_m A[n,m] G[m,t];  P[n,t] = sum_m B[n,m] G[m,t]^2  (full m-sum)
// Thread (ms = tid>>4, ts = tid&15): m-slice of 16 rows, one float4 t-column group.
__global__ __launch_bounds__(256, 2) void k_main(
    const float* __restrict__ W2, const float* __restrict__ W3,
    const float* __restrict__ b2, float* __restrict__ out)
{
    __shared__ float4 sP4[8 * 256];      // [comp(4M+4P)][ms*16+ts] = 32KB
    __shared__ float4 sA4[H], sB4[H];    // A/B coeffs for 4 n (8KB)
    __shared__ float4 sU4[64];           // U coeffs for this quarter's 64 t (1KB)
    __shared__ float  sredA[8][12];
    __shared__ float  sredQ[8][4];
    __shared__ double sdr[8];

    int tid = threadIdx.x;
    int bx = blockIdx.x;
    int q = bx >> 2, qt = bx & 3;
    int wid = tid >> 5, lane = tid & 31;
    int n0 = 4 * q;

    // ---- setup: coefficient vectors for 4 n ----
    float w2a, w2b, w2c, w2d, h1v, h2v;
    {
        int m = tid;
        h1v = g_h1[m]; h2v = g_h2[m];
        w2a = __ldg(&W2[(n0 + 0) * H + m]);
        w2b = __ldg(&W2[(n0 + 1) * H + m]);
        w2c = __ldg(&W2[(n0 + 2) * H + m]);
        w2d = __ldg(&W2[(n0 + 3) * H + m]);
        sA4[m] = make_float4(w2a * h1v, w2b * h1v, w2c * h1v, w2d * h1v);
        sB4[m] = make_float4(w2a * h2v, w2b * h2v, w2c * h2v, w2d * h2v);
        if (tid < 64) {
            int gt = qt * 64 + tid;
            float u3 = g_u3[gt];
            sU4[tid] = make_float4(__ldg(&W2[(n0 + 0) * H + gt]) * u3,
                                   __ldg(&W2[(n0 + 1) * H + gt]) * u3,
                                   __ldg(&W2[(n0 + 2) * H + gt]) * u3,
                                   __ldg(&W2[(n0 + 3) * H + gt]) * u3);
        }
    }
    // qt==0 blocks publish a/L/Y (12 values per quad)
    if (qt == 0) {
        float hh = g_h[tid], h2s = g_h2s[tid], h4s2 = g_h4s2[tid];
        float v[12];
        v[0] = w2a * hh;  v[1]  = w2a * h2s;  v[2]  = w2a * h4s2;
        v[3] = w2b * hh;  v[4]  = w2b * h2s;  v[5]  = w2b * h4s2;
        v[6] = w2c * hh;  v[7]  = w2c * h2s;  v[8]  = w2c * h4s2;
        v[9] = w2d * hh;  v[10] = w2d * h2s;  v[11] = w2d * h4s2;
#pragma unroll
        for (int k = 0; k < 12; k++) {
            float t = v[k];
#pragma unroll
            for (int o = 16; o > 0; o >>= 1) t += __shfl_down_sync(0xFFFFFFFFu, t, o);
            v[k] = t;
        }
        if (lane == 0) {
#pragma unroll
            for (int k = 0; k < 12; k++) sredA[wid][k] = v[k];
        }
    }
    __syncthreads();
    if (qt == 0 && tid < 12) {
        float t = 0.f;
#pragma unroll
        for (int w = 0; w < 8; w++) t += sredA[w][tid];
        g_aLY[q][tid] = t;
    }

    // ---- phase 1: pipelined G stream, 4n x 4t micro-tile ----
    int ms = tid >> 4, ts = tid & 15;
    float M[4][4] = {{0}}, P[4][4] = {{0}};

    const float4* Gp = (const float4*)g_G + (16 * ms) * (H / 4) + qt * 16 + ts;
    const float4* ap = sA4 + 16 * ms;
    const float4* bp = sB4 + 16 * ms;

    float4 buf[2][4];
#pragma unroll
    for (int u = 0; u < 4; u++) buf[0][u] = __ldg(Gp + u * (H / 4));

#pragma unroll
    for (int bb = 0; bb < 4; bb++) {
        int cur = bb & 1, nxt = cur ^ 1;
        if (bb < 3) {
#pragma unroll
            for (int u = 0; u < 4; u++)
                buf[nxt][u] = __ldg(Gp + (4 * (bb + 1) + u) * (H / 4));
        }
#pragma unroll
        for (int u = 0; u < 4; u++) {
            float4 g = buf[cur][u];
            float4 a = ap[4 * bb + u];
            float4 b = bp[4 * bb + u];
            float gg0 = g.x * g.x, gg1 = g.y * g.y, gg2 = g.z * g.z, gg3 = g.w * g.w;
            M[0][0] += a.x * g.x;  M[0][1] += a.x * g.y;  M[0][2] += a.x * g.z;  M[0][3] += a.x * g.w;
            M[1][0] += a.y * g.x;  M[1][1] += a.y * g.y;  M[1][2] += a.y * g.z;  M[1][3] += a.y * g.w;
            M[2][0] += a.z * g.x;  M[2][1] += a.z * g.y;  M[2][2] += a.z * g.z;  M[2][3] += a.z * g.w;
            M[3][0] += a.w * g.x;  M[3][1] += a.w * g.y;  M[3][2] += a.w * g.z;  M[3][3] += a.w * g.w;
            P[0][0] += b.x * gg0;  P[0][1] += b.x * gg1;  P[0][2] += b.x * gg2;  P[0][3] += b.x * gg3;
            P[1][0] += b.y * gg0;  P[1][1] += b.y * gg1;  P[1][2] += b.y * gg2;  P[1][3] += b.y * gg3;
            P[2][0] += b.z * gg0;  P[2][1] += b.z * gg1;  P[2][2] += b.z * gg2;  P[2][3] += b.z * gg3;
            P[3][0] += b.w * gg0;  P[3][1] += b.w * gg1;  P[3][2] += b.w * gg2;  P[3][3] += b.w * gg3;
        }
    }

    // write partials: layout [comp][ms*16+ts], comp = n (M) / 4+n (P)
    {
        float4* sp = sP4 + ms * 16 + ts;
#pragma unroll
        for (int n = 0; n < 4; n++)
            sp[n * 256] = make_float4(M[n][0], M[n][1], M[n][2], M[n][3]);
#pragma unroll
        for (int n = 0; n < 4; n++)
            sp[(4 + n) * 256] = make_float4(P[n][0], P[n][1], P[n][2], P[n][3]);
    }
    __syncthreads();

    // ---- phase 2: combine 16 m-slices + contraction; thread = (n = tid>>6, tloc = tid&63) ----
    {
        int n = tid >> 6, tloc = tid & 63;
        int ts2 = tloc >> 2, c = tloc & 3;
        const float* base = (const float*)sP4;
        float m0 = 0.f, p0 = 0.f;
#pragma unroll
        for (int w = 0; w < 16; w++) {
            m0 += base[(n * 256 + w * 16 + ts2) * 4 + c];
            p0 += base[((4 + n) * 256 + w * 16 + ts2) * 4 + c];
        }
        int gt = qt * 64 + tloc;
        float A = ((const float*)sA4)[gt * 4 + n];
        float B = ((const float*)sB4)[gt * 4 + n];
        float U = ((const float*)sU4)[tloc * 4 + n];
        float qv = A * m0;
        float rv = B * m0 * m0;
        float zv = B * p0;
        float uv = U * m0;
#pragma unroll
        for (int o = 16; o > 0; o >>= 1) {
            qv += __shfl_down_sync(0xFFFFFFFFu, qv, o);
            rv += __shfl_down_sync(0xFFFFFFFFu, rv, o);
            zv += __shfl_down_sync(0xFFFFFFFFu, zv, o);
            uv += __shfl_down_sync(0xFFFFFFFFu, uv, o);
        }
        if (lane == 0) {
            sredQ[wid][0] = qv;  sredQ[wid][1] = rv;
            sredQ[wid][2] = zv;  sredQ[wid][3] = uv;
        }
    }
    __syncthreads();
    if (tid < 16) {
        int n = tid >> 2, cc = tid & 3;
        float t = sredQ[2 * n][cc] + sredQ[2 * n + 1][cc];
        atomicAdd(&g_QRZU[q][n * 4 + cc], t);
    }

    // ---- global ticket: one block runs the nonlinear tail ----
    __threadfence();
    __shared__ unsigned int slast;
    if (tid == 0) slast = (atomicAdd(&g_done, 1u) == NBM - 1) ? 1u : 0u;
    __syncthreads();
    if (slast) {
        __threadfence();
        int n = tid;
        int qq = n >> 2, sel = n & 3;
        float Q = g_QRZU[qq][sel * 4 + 0];
        float R = g_QRZU[qq][sel * 4 + 1];
        float Z = g_QRZU[qq][sel * 4 + 2];
        float U = g_QRZU[qq][sel * 4 + 3];
        float a = g_aLY[qq][3 * sel + 0] + b2[n];
        float L = g_aLY[qq][3 * sel + 1];
        float Y = g_aLY[qq][3 * sel + 2];
        float g = tanhf(a), gw = 1.f - g * g;
        float g1 = gw;
        float g2 = -2.f * g * gw;
        float g3 = (4.f * g * g - 2.f * gw) * gw;
        float g4 = (16.f * gw - 8.f * g * g) * g * gw;
        float val = g4 * Q * Q
                  + g3 * (2.f * L * Q + 4.f * R)
                  + g2 * (L * L + 2.f * Z + 4.f * U)
                  + g1 * Y;
        double d = (double)(__ldg(&W3[n]) * val);
#pragma unroll
        for (int o = 16; o > 0; o >>= 1) d += __shfl_down_sync(0xFFFFFFFFu, d, o);
        if (lane == 0) sdr[wid] = d;
        __syncthreads();
        if (wid == 0) {
            double v = (lane < 8) ? sdr[lane] : 0.0;
#pragma unroll
            for (int o = 4; o > 0; o >>= 1) v += __shfl_down_sync(0xFFu, v, o);
            if (lane == 0) {
                out[0] = (float)v;
                g_done = 0u;       // reset for next graph replay
                __threadfence();
            }
        }
    }
}

// ---------------- launch ----------------
extern "C" void kernel_launch(void* const* d_in, const int* in_sizes, int n_in,
                              void* d_out, int out_size) {
    const float* x  = (const float*)d_in[0];
    const float* W1 = (const float*)d_in[1];
    const float* b1 = (const float*)d_in[2];
    const float* W2 = (const float*)d_in[3];
    const float* b2 = (const float*)d_in[4];
    const float* W3 = (const float*)d_in[5];
    // d_in[6] = b3: does not affect the 4th derivative
    float* out = (float*)d_out;

    k_pre<<<128, 256>>>(x, W1, b1);
    k_main<<<NBM, 256>>>(W2, W3, b2, out);
}